// round 8
// baseline (speedup 1.0000x reference)
#include <cuda_runtime.h>
#include <cuda_bf16.h>
#include <cstdint>

// Problem constants (fixed shapes for TrivialDecoder_1236950581455)
#define E_GROUPS 65536
#define KNEG     16
#define GROUP    17
#define PAIRS    (E_GROUPS * GROUP)   // 1,114,112
#define D        64
#define KDIM     192
#define M_TILE   128
#define NTILE_TOT (PAIRS / M_TILE)    // 8704
#define THREADS  128                  // 4 warps, each owns 32 m-rows
#define KSTEPS   12                   // 192 / 16
#define NTILES   8                    // 64 / 8
#define GRID_SC  444                  // 148 SMs x 3 CTAs

#define APITCH   384                  // A: bytes per row (XOR-swizzled 16B chunks)
#define BPITCH   384                  // B: bytes per row (XOR-swizzled 16B chunks)

// SMEM byte layout: total 74752 B (~73 KB) -> 3 CTAs/SM
#define SMEM_B1    0                          // 64 floats
#define SMEM_W2    256                        // 64 floats
#define SMEM_A     1024                       // 128 x 384 B = 49152 B
#define SMEM_B     (1024 + 128 * APITCH)      // 64 x 384 B = 24576 B
#define SMEM_TOTAL (SMEM_B + 64 * BPITCH)     // 74752

__device__ float g_scores[PAIRS];

__global__ void zero_out_kernel(float* out) { out[0] = 0.0f; }

// ---------------- portable PTX helpers ----------------
__device__ __forceinline__ uint32_t smem_u32(const void* p) {
    uint32_t a;
    asm("{ .reg .u64 t; cvta.to.shared.u64 t, %1; cvt.u32.u64 %0, t; }" : "=r"(a) : "l"(p));
    return a;
}

__device__ __forceinline__ void ldmatrix_x4(uint32_t* r, uint32_t addr) {
    asm volatile("ldmatrix.sync.aligned.m8n8.x4.shared.b16 {%0,%1,%2,%3}, [%4];"
                 : "=r"(r[0]), "=r"(r[1]), "=r"(r[2]), "=r"(r[3]) : "r"(addr));
}
__device__ __forceinline__ void ldmatrix_x2(uint32_t* r, uint32_t addr) {
    asm volatile("ldmatrix.sync.aligned.m8n8.x2.shared.b16 {%0,%1}, [%2];"
                 : "=r"(r[0]), "=r"(r[1]) : "r"(addr));
}
__device__ __forceinline__ void mma_16816(float* c, const uint32_t* a, const uint32_t* b) {
    asm volatile(
        "mma.sync.aligned.m16n8k16.row.col.f32.bf16.bf16.f32 "
        "{%0,%1,%2,%3}, {%4,%5,%6,%7}, {%8,%9}, {%0,%1,%2,%3};"
        : "+f"(c[0]), "+f"(c[1]), "+f"(c[2]), "+f"(c[3])
        : "r"(a[0]), "r"(a[1]), "r"(a[2]), "r"(a[3]), "r"(b[0]), "r"(b[1]));
}

__device__ __forceinline__ uint32_t pack2(float a, float b) {
    __nv_bfloat162 h = __float22bfloat162_rn(make_float2(a, b));
    return *reinterpret_cast<uint32_t*>(&h);
}

// B tile swizzle: row n (384 B pitch), 16B-chunk ch in [0,24): ch ^= (n & 7)
__device__ __forceinline__ int b_byte(int n, int ch) {
    return SMEM_B + n * BPITCH + ((ch ^ (n & 7)) << 4);
}

// ---------------------------------------------------------------------------
// Kernel 1: persistent, barrier-free warp pipelines; 4 warps x 32 m-rows.
// Each B fragment feeds two m16 mma ops (halved B ldmatrix traffic).
// ---------------------------------------------------------------------------
__global__ void __launch_bounds__(THREADS, 3)
score_kernel(const float* __restrict__ embeds,
             const int*   __restrict__ pos,
             const int*   __restrict__ neg,
             const float* __restrict__ W1,
             const float* __restrict__ b1,
             const float* __restrict__ W2,
             const float* __restrict__ b2)
{
    extern __shared__ char smem[];
    const uint32_t sbase = smem_u32(smem);
    const int tid = threadIdx.x;
    const int wid = tid >> 5;
    const int lid = tid & 31;

    // One-time staging: b1, W2, W1 (bf16, swizzled B tile).
    if (tid < 64) {
        ((float*)(smem + SMEM_B1))[tid] = b1[tid];
        ((float*)(smem + SMEM_W2))[tid] = W2[tid];
    }
    for (int c = tid; c < 64 * 24; c += THREADS) {
        int n  = c / 24;
        int ch = c - n * 24;
        const float4* wp = (const float4*)(W1 + n * KDIM + ch * 8);
        float4 w0 = wp[0], w1 = wp[1];
        uint4 v = make_uint4(pack2(w0.x, w0.y), pack2(w0.z, w0.w),
                             pack2(w1.x, w1.y), pack2(w1.z, w1.w));
        *(uint4*)(smem + b_byte(n, ch)) = v;
    }
    __syncthreads();   // only barrier in the kernel

    const float b2v = b2[0];
    const int q   = lid & 15;          // float4 slot within a 64-float row
    const int grp = lid >> 4;          // which of two rows per gather iter
    const int qh  = q >> 1;            // 16B chunk within 128B segment
    const int qo  = (q & 1) * 8;       // 8B half within chunk

    // A ldmatrix addressing (rows rowA0 / rowA0+16 share the same swizzle key)
    const int rowA0  = wid * 32 + (lid & 15);
    const uint32_t aoff0 = sbase + SMEM_A + rowA0 * APITCH;
    const uint32_t aoff1 = aoff0 + 16 * APITCH;
    const int rxA = rowA0 & 7;
    const int ah  = lid >> 4;

    // B ldmatrix addressing (same scheme as staging)
    const uint32_t b_row0 = sbase + SMEM_B + (lid & 7) * BPITCH;
    const int      b_xor  = (lid & 7);
    const int      b_h    = (lid >> 3) & 1;

    for (int t = blockIdx.x; t < NTILE_TOT; t += GRID_SC) {
        const int p0 = t * M_TILE;

        // ---- gather + convert: warp owns rows [32*wid, 32*wid+32) ----
        int iu_r, iv_r;
        {
            int p = p0 + wid * 32 + lid;
            unsigned e = (unsigned)p / 17u;
            unsigned j = (unsigned)p - e * 17u;
            const int* pr = (j == 0) ? (pos + 2 * e)
                                     : (neg + 2 * (e * KNEG + (j - 1)));
            iu_r = pr[0];
            iv_r = pr[1];
        }
        #pragma unroll
        for (int it = 0; it < 16; it++) {
            int src = 2 * it + grp;                       // local row 0..31
            int iu = __shfl_sync(0xffffffffu, iu_r, src);
            int iv = __shfl_sync(0xffffffffu, iv_r, src);
            float4 u4 = ((const float4*)(embeds + (size_t)iu * 64))[q];
            float4 v4 = ((const float4*)(embeds + (size_t)iv * 64))[q];
            int row = wid * 32 + src;
            char* xr = smem + SMEM_A + row * APITCH;
            int rx = row & 7;
            *(uint2*)(xr + (((qh     ) ^ rx) << 4) + qo) =
                make_uint2(pack2(u4.x, u4.y), pack2(u4.z, u4.w));
            *(uint2*)(xr + (((qh +  8) ^ rx) << 4) + qo) =
                make_uint2(pack2(v4.x, v4.y), pack2(v4.z, v4.w));
            *(uint2*)(xr + (((qh + 16) ^ rx) << 4) + qo) =
                make_uint2(pack2(u4.x * v4.x, u4.y * v4.y),
                           pack2(u4.z * v4.z, u4.w * v4.w));
        }

        // ---- GEMM: warp tile 32(m) x 64(n), K=192 ----
        float c0[NTILES][4], c1[NTILES][4];
        #pragma unroll
        for (int nt = 0; nt < NTILES; nt++) {
            c0[nt][0] = c0[nt][1] = c0[nt][2] = c0[nt][3] = 0.0f;
            c1[nt][0] = c1[nt][1] = c1[nt][2] = c1[nt][3] = 0.0f;
        }
        #pragma unroll
        for (int ks = 0; ks < KSTEPS; ks++) {
            uint32_t a0[4], a1[4];
            uint32_t chA = (uint32_t)(((ks * 2 + ah) ^ rxA) << 4);
            ldmatrix_x4(a0, aoff0 + chA);
            ldmatrix_x4(a1, aoff1 + chA);
            uint32_t chB = (uint32_t)(((ks * 2 + b_h) ^ b_xor) << 4);
            #pragma unroll
            for (int nt = 0; nt < NTILES; nt++) {
                uint32_t b[2];
                ldmatrix_x2(b, b_row0 + nt * 8 * BPITCH + chB);
                mma_16816(c0[nt], a0, b);
                mma_16816(c1[nt], a1, b);
            }
        }

        // ---- epilogue in fragment layout (both m-halves) ----
        const float* b1s = (const float*)(smem + SMEM_B1);
        const float* w2s = (const float*)(smem + SMEM_W2);
        float z00 = 0.0f, z01 = 0.0f, z10 = 0.0f, z11 = 0.0f;
        #pragma unroll
        for (int nt = 0; nt < NTILES; nt++) {
            int n0 = nt * 8 + 2 * (lid & 3);
            float bb0 = b1s[n0], bb1 = b1s[n0 + 1];
            float ww0 = w2s[n0], ww1 = w2s[n0 + 1];
            float h;
            h = c0[nt][0] + bb0; h = h > 0.0f ? h : 0.0f; z00 += h * ww0;
            h = c0[nt][1] + bb1; h = h > 0.0f ? h : 0.0f; z00 += h * ww1;
            h = c0[nt][2] + bb0; h = h > 0.0f ? h : 0.0f; z01 += h * ww0;
            h = c0[nt][3] + bb1; h = h > 0.0f ? h : 0.0f; z01 += h * ww1;
            h = c1[nt][0] + bb0; h = h > 0.0f ? h : 0.0f; z10 += h * ww0;
            h = c1[nt][1] + bb1; h = h > 0.0f ? h : 0.0f; z10 += h * ww1;
            h = c1[nt][2] + bb0; h = h > 0.0f ? h : 0.0f; z11 += h * ww0;
            h = c1[nt][3] + bb1; h = h > 0.0f ? h : 0.0f; z11 += h * ww1;
        }
        z00 += __shfl_xor_sync(0xffffffffu, z00, 1);
        z00 += __shfl_xor_sync(0xffffffffu, z00, 2);
        z01 += __shfl_xor_sync(0xffffffffu, z01, 1);
        z01 += __shfl_xor_sync(0xffffffffu, z01, 2);
        z10 += __shfl_xor_sync(0xffffffffu, z10, 1);
        z10 += __shfl_xor_sync(0xffffffffu, z10, 2);
        z11 += __shfl_xor_sync(0xffffffffu, z11, 1);
        z11 += __shfl_xor_sync(0xffffffffu, z11, 2);

        if ((lid & 3) == 0) {
            int r = p0 + wid * 32 + (lid >> 2);
            float s00 = 1.0f / (1.0f + expf(-(z00 + b2v)));
            float s01 = 1.0f / (1.0f + expf(-(z01 + b2v)));
            float s10 = 1.0f / (1.0f + expf(-(z10 + b2v)));
            float s11 = 1.0f / (1.0f + expf(-(z11 + b2v)));
            g_scores[r]      = expf(s00);
            g_scores[r + 8]  = expf(s01);
            g_scores[r + 16] = expf(s10);
            g_scores[r + 24] = expf(s11);
        }
    }
}

// ---------------------------------------------------------------------------
// Kernel 2: per-group ratio + global reduction.
// ---------------------------------------------------------------------------
__global__ void __launch_bounds__(256)
loss_kernel(float* __restrict__ out)
{
    int e = blockIdx.x * blockDim.x + threadIdx.x;
    float term = 0.0f;
    if (e < E_GROUPS) {
        const float* s = g_scores + (long long)e * GROUP;
        float ps = s[0];
        float denom = ps;
        #pragma unroll
        for (int j = 1; j < GROUP; j++) denom += s[j];
        term = ps / (denom + 1e-8f) + 1e-8f;
    }
    #pragma unroll
    for (int o = 16; o; o >>= 1) term += __shfl_xor_sync(0xffffffffu, term, o);

    __shared__ float wsum[8];
    int l = threadIdx.x & 31;
    int w = threadIdx.x >> 5;
    if (l == 0) wsum[w] = term;
    __syncthreads();
    if (threadIdx.x < 8) {
        float t = wsum[threadIdx.x];
        #pragma unroll
        for (int o = 4; o; o >>= 1) t += __shfl_xor_sync(0x000000ffu, t, o);
        if (threadIdx.x == 0) atomicAdd(out, -t);
    }
}

extern "C" void kernel_launch(void* const* d_in, const int* in_sizes, int n_in,
                              void* d_out, int out_size)
{
    const float* embeds = (const float*)d_in[0];
    const int*   pos    = (const int*)  d_in[1];
    const int*   neg    = (const int*)  d_in[2];
    const float* W1     = (const float*)d_in[3];
    const float* b1     = (const float*)d_in[4];
    const float* W2     = (const float*)d_in[5];
    const float* b2     = (const float*)d_in[6];
    float*       out    = (float*)d_out;

    cudaFuncSetAttribute(score_kernel, cudaFuncAttributeMaxDynamicSharedMemorySize,
                         SMEM_TOTAL);

    zero_out_kernel<<<1, 1>>>(out);
    score_kernel<<<GRID_SC, THREADS, SMEM_TOTAL>>>(embeds, pos, neg, W1, b1, W2, b2);
    loss_kernel<<<E_GROUPS / 256, 256>>>(out);
}

// round 9
// speedup vs baseline: 1.1437x; 1.1437x over previous
#include <cuda_runtime.h>
#include <cuda_bf16.h>
#include <cstdint>

// Problem constants (fixed shapes for TrivialDecoder_1236950581455)
#define E_GROUPS 65536
#define KNEG     16
#define GROUP    17
#define PAIRS    (E_GROUPS * GROUP)   // 1,114,112
#define D        64
#define KDIM     192
#define M_TILE   128
#define NTILE_TOT (PAIRS / M_TILE)    // 8704
#define THREADS  128                  // 4 warps, each owns 32 m-rows
#define KSTEPS   6                    // 192 / 32 (fp8 k32 mma)
#define NTILES   8                    // 64 / 8
#define GRID_SC  592                  // 148 SMs x 4 CTAs

#define APITCH   208                  // A: bytes per row (e4m3), conflict-free LDS
#define BPITCH   208                  // B: bytes per row (e4m3)

// SMEM byte layout: total 40960 B (40 KB) -> 4 CTAs/SM
#define SMEM_B1    0                          // 64 floats
#define SMEM_W2    256                        // 64 floats
#define SMEM_A     1024                       // 128 x 208 = 26624 B
#define SMEM_B     (1024 + 128 * APITCH)      // 64 x 208 = 13312 B
#define SMEM_TOTAL (SMEM_B + 64 * BPITCH)     // 40960

__device__ float g_scores[PAIRS];

__global__ void zero_out_kernel(float* out) { out[0] = 0.0f; }

// ---------------- portable PTX helpers ----------------
// cvt.e4m3x2: a -> high byte, b -> low byte. We want k-ascending in ascending bytes.
__device__ __forceinline__ uint32_t pack4_e4m3(float x0, float x1, float x2, float x3) {
    uint16_t lo, hi;
    asm("cvt.rn.satfinite.e4m3x2.f32 %0, %1, %2;" : "=h"(lo) : "f"(x1), "f"(x0));
    asm("cvt.rn.satfinite.e4m3x2.f32 %0, %1, %2;" : "=h"(hi) : "f"(x3), "f"(x2));
    return (uint32_t)lo | ((uint32_t)hi << 16);
}

__device__ __forceinline__ void mma_16832_e4m3(float* c, const uint32_t* a, const uint32_t* b) {
    asm volatile(
        "mma.sync.aligned.m16n8k32.row.col.f32.e4m3.e4m3.f32 "
        "{%0,%1,%2,%3}, {%4,%5,%6,%7}, {%8,%9}, {%0,%1,%2,%3};"
        : "+f"(c[0]), "+f"(c[1]), "+f"(c[2]), "+f"(c[3])
        : "r"(a[0]), "r"(a[1]), "r"(a[2]), "r"(a[3]), "r"(b[0]), "r"(b[1]));
}

// ---------------------------------------------------------------------------
// Kernel 1: persistent, barrier-free warp pipelines; 4 warps x 32 m-rows.
// GEMM on fp8 e4m3 (m16n8k32), fp32 accumulate. W1 scaled x8 -> epilogue x0.125.
// Fragments built with plain LDS.32 (208 B pitch => conflict-free pattern).
// ---------------------------------------------------------------------------
__global__ void __launch_bounds__(THREADS, 4)
score_kernel(const float* __restrict__ embeds,
             const int*   __restrict__ pos,
             const int*   __restrict__ neg,
             const float* __restrict__ W1,
             const float* __restrict__ b1,
             const float* __restrict__ W2,
             const float* __restrict__ b2)
{
    extern __shared__ char smem[];
    const int tid = threadIdx.x;
    const int wid = tid >> 5;
    const int lid = tid & 31;
    const int g   = lid >> 2;          // fragment row/col group
    const int tg  = lid & 3;           // thread-in-group

    // One-time staging: b1, W2, W1 (e4m3 x8, plain 208B-pitch rows).
    if (tid < 64) {
        ((float*)(smem + SMEM_B1))[tid] = b1[tid];
        ((float*)(smem + SMEM_W2))[tid] = W2[tid];
    }
    for (int c = tid; c < 64 * 12; c += THREADS) {
        int n  = c / 12;
        int gq = c - n * 12;                    // 16-k chunk within row
        const float4* wp = (const float4*)(W1 + n * KDIM + gq * 16);
        float4 w0 = wp[0], w1 = wp[1], w2c = wp[2], w3 = wp[3];
        uint4 v = make_uint4(
            pack4_e4m3(w0.x * 8.0f, w0.y * 8.0f, w0.z * 8.0f, w0.w * 8.0f),
            pack4_e4m3(w1.x * 8.0f, w1.y * 8.0f, w1.z * 8.0f, w1.w * 8.0f),
            pack4_e4m3(w2c.x * 8.0f, w2c.y * 8.0f, w2c.z * 8.0f, w2c.w * 8.0f),
            pack4_e4m3(w3.x * 8.0f, w3.y * 8.0f, w3.z * 8.0f, w3.w * 8.0f));
        *(uint4*)(smem + SMEM_B + n * BPITCH + gq * 16) = v;
    }
    __syncthreads();   // only barrier in the kernel

    const float b2v = b2[0];
    const int q   = lid & 15;          // float4 slot within a 64-float row
    const int grp = lid >> 4;          // which of two rows per gather iter

    for (int t = blockIdx.x; t < NTILE_TOT; t += GRID_SC) {
        const int p0 = t * M_TILE;

        // ---- gather + convert: warp owns rows [32*wid, 32*wid+32) ----
        int iu_r, iv_r;
        {
            int p = p0 + wid * 32 + lid;
            unsigned e = (unsigned)p / 17u;
            unsigned j = (unsigned)p - e * 17u;
            const int* pr = (j == 0) ? (pos + 2 * e)
                                     : (neg + 2 * (e * KNEG + (j - 1)));
            iu_r = pr[0];
            iv_r = pr[1];
        }
        #pragma unroll
        for (int it = 0; it < 16; it++) {
            int src = 2 * it + grp;                       // local row 0..31
            int iu = __shfl_sync(0xffffffffu, iu_r, src);
            int iv = __shfl_sync(0xffffffffu, iv_r, src);
            float4 u4 = ((const float4*)(embeds + (size_t)iu * 64))[q];
            float4 v4 = ((const float4*)(embeds + (size_t)iv * 64))[q];
            char* xr = smem + SMEM_A + (wid * 32 + src) * APITCH;
            *(uint32_t*)(xr + q * 4) =
                pack4_e4m3(u4.x, u4.y, u4.z, u4.w);
            *(uint32_t*)(xr + 64 + q * 4) =
                pack4_e4m3(v4.x, v4.y, v4.z, v4.w);
            *(uint32_t*)(xr + 128 + q * 4) =
                pack4_e4m3(u4.x * v4.x, u4.y * v4.y, u4.z * v4.z, u4.w * v4.w);
        }

        // ---- GEMM: warp tile 32(m) x 64(n), K=192 (6 k32 steps) ----
        float c0[NTILES][4], c1[NTILES][4];
        #pragma unroll
        for (int nt = 0; nt < NTILES; nt++) {
            c0[nt][0] = c0[nt][1] = c0[nt][2] = c0[nt][3] = 0.0f;
            c1[nt][0] = c1[nt][1] = c1[nt][2] = c1[nt][3] = 0.0f;
        }
        #pragma unroll
        for (int ks = 0; ks < KSTEPS; ks++) {
            uint32_t a0[4], a1[4];
            {
                const char* ar = smem + SMEM_A + (wid * 32 + g) * APITCH + ks * 32 + tg * 4;
                a0[0] = *(const uint32_t*)(ar);
                a0[1] = *(const uint32_t*)(ar + 8 * APITCH);
                a0[2] = *(const uint32_t*)(ar + 16);
                a0[3] = *(const uint32_t*)(ar + 8 * APITCH + 16);
                const char* ar1 = ar + 16 * APITCH;
                a1[0] = *(const uint32_t*)(ar1);
                a1[1] = *(const uint32_t*)(ar1 + 8 * APITCH);
                a1[2] = *(const uint32_t*)(ar1 + 16);
                a1[3] = *(const uint32_t*)(ar1 + 8 * APITCH + 16);
            }
            #pragma unroll
            for (int nt = 0; nt < NTILES; nt++) {
                uint32_t b[2];
                const char* br = smem + SMEM_B + (nt * 8 + g) * BPITCH + ks * 32 + tg * 4;
                b[0] = *(const uint32_t*)(br);
                b[1] = *(const uint32_t*)(br + 16);
                mma_16832_e4m3(c0[nt], a0, b);
                mma_16832_e4m3(c1[nt], a1, b);
            }
        }

        // ---- epilogue in fragment layout (x0.125 undoes the W1 x8 scale) ----
        const float* b1s = (const float*)(smem + SMEM_B1);
        const float* w2s = (const float*)(smem + SMEM_W2);
        float z00 = 0.0f, z01 = 0.0f, z10 = 0.0f, z11 = 0.0f;
        #pragma unroll
        for (int nt = 0; nt < NTILES; nt++) {
            int n0 = nt * 8 + 2 * tg;
            float bb0 = b1s[n0], bb1 = b1s[n0 + 1];
            float ww0 = w2s[n0], ww1 = w2s[n0 + 1];
            float h;
            h = fmaf(c0[nt][0], 0.125f, bb0); h = h > 0.0f ? h : 0.0f; z00 += h * ww0;
            h = fmaf(c0[nt][1], 0.125f, bb1); h = h > 0.0f ? h : 0.0f; z00 += h * ww1;
            h = fmaf(c0[nt][2], 0.125f, bb0); h = h > 0.0f ? h : 0.0f; z01 += h * ww0;
            h = fmaf(c0[nt][3], 0.125f, bb1); h = h > 0.0f ? h : 0.0f; z01 += h * ww1;
            h = fmaf(c1[nt][0], 0.125f, bb0); h = h > 0.0f ? h : 0.0f; z10 += h * ww0;
            h = fmaf(c1[nt][1], 0.125f, bb1); h = h > 0.0f ? h : 0.0f; z10 += h * ww1;
            h = fmaf(c1[nt][2], 0.125f, bb0); h = h > 0.0f ? h : 0.0f; z11 += h * ww0;
            h = fmaf(c1[nt][3], 0.125f, bb1); h = h > 0.0f ? h : 0.0f; z11 += h * ww1;
        }
        z00 += __shfl_xor_sync(0xffffffffu, z00, 1);
        z00 += __shfl_xor_sync(0xffffffffu, z00, 2);
        z01 += __shfl_xor_sync(0xffffffffu, z01, 1);
        z01 += __shfl_xor_sync(0xffffffffu, z01, 2);
        z10 += __shfl_xor_sync(0xffffffffu, z10, 1);
        z10 += __shfl_xor_sync(0xffffffffu, z10, 2);
        z11 += __shfl_xor_sync(0xffffffffu, z11, 1);
        z11 += __shfl_xor_sync(0xffffffffu, z11, 2);

        if (tg == 0) {
            int r = p0 + wid * 32 + g;
            float s00 = 1.0f / (1.0f + expf(-(z00 + b2v)));
            float s01 = 1.0f / (1.0f + expf(-(z01 + b2v)));
            float s10 = 1.0f / (1.0f + expf(-(z10 + b2v)));
            float s11 = 1.0f / (1.0f + expf(-(z11 + b2v)));
            g_scores[r]      = expf(s00);
            g_scores[r + 8]  = expf(s01);
            g_scores[r + 16] = expf(s10);
            g_scores[r + 24] = expf(s11);
        }
    }
}

// ---------------------------------------------------------------------------
// Kernel 2: per-group ratio + global reduction.
// ---------------------------------------------------------------------------
__global__ void __launch_bounds__(256)
loss_kernel(float* __restrict__ out)
{
    int e = blockIdx.x * blockDim.x + threadIdx.x;
    float term = 0.0f;
    if (e < E_GROUPS) {
        const float* s = g_scores + (long long)e * GROUP;
        float ps = s[0];
        float denom = ps;
        #pragma unroll
        for (int j = 1; j < GROUP; j++) denom += s[j];
        term = ps / (denom + 1e-8f) + 1e-8f;
    }
    #pragma unroll
    for (int o = 16; o; o >>= 1) term += __shfl_xor_sync(0xffffffffu, term, o);

    __shared__ float wsum[8];
    int l = threadIdx.x & 31;
    int w = threadIdx.x >> 5;
    if (l == 0) wsum[w] = term;
    __syncthreads();
    if (threadIdx.x < 8) {
        float t = wsum[threadIdx.x];
        #pragma unroll
        for (int o = 4; o; o >>= 1) t += __shfl_xor_sync(0x000000ffu, t, o);
        if (threadIdx.x == 0) atomicAdd(out, -t);
    }
}

extern "C" void kernel_launch(void* const* d_in, const int* in_sizes, int n_in,
                              void* d_out, int out_size)
{
    const float* embeds = (const float*)d_in[0];
    const int*   pos    = (const int*)  d_in[1];
    const int*   neg    = (const int*)  d_in[2];
    const float* W1     = (const float*)d_in[3];
    const float* b1     = (const float*)d_in[4];
    const float* W2     = (const float*)d_in[5];
    const float* b2     = (const float*)d_in[6];
    float*       out    = (float*)d_out;

    cudaFuncSetAttribute(score_kernel, cudaFuncAttributeMaxDynamicSharedMemorySize,
                         SMEM_TOTAL);

    zero_out_kernel<<<1, 1>>>(out);
    score_kernel<<<GRID_SC, THREADS, SMEM_TOTAL>>>(embeds, pos, neg, W1, b1, W2, b2);
    loss_kernel<<<E_GROUPS / 256, 256>>>(out);
}

// round 10
// speedup vs baseline: 1.1454x; 1.0015x over previous
#include <cuda_runtime.h>
#include <cuda_bf16.h>
#include <cstdint>

// Problem constants (fixed shapes for TrivialDecoder_1236950581455)
#define E_GROUPS 65536
#define KNEG     16
#define GROUP    17
#define PAIRS    (E_GROUPS * GROUP)   // 1,114,112
#define D        64
#define KDIM     192
#define M_TILE   128
#define NTILE_TOT (PAIRS / M_TILE)    // 8704
#define THREADS  128                  // 4 warps, each owns 32 m-rows
#define KSTEPS   6                    // 192 / 32 (fp8 k32 mma)
#define NTILES   8                    // 64 / 8
#define GRID_SC  592                  // 148 SMs x 4 CTAs

#define APITCH   208                  // A: bytes per row (e4m3), conflict-free LDS
#define BPITCH   208                  // B: bytes per row (e4m3)

// SMEM byte layout: total 40960 B (40 KB) -> 4 CTAs/SM
#define SMEM_B1    0                          // 64 floats
#define SMEM_W2    256                        // 64 floats
#define SMEM_A     1024                       // 128 x 208 = 26624 B
#define SMEM_B     (1024 + 128 * APITCH)      // 64 x 208 = 13312 B
#define SMEM_TOTAL (SMEM_B + 64 * BPITCH)     // 40960

__device__ float g_scores[PAIRS];

__global__ void zero_out_kernel(float* out) { out[0] = 0.0f; }

// ---------------- portable PTX helpers ----------------
// cvt.e4m3x2: a -> high byte, b -> low byte. We want k-ascending in ascending bytes.
__device__ __forceinline__ uint32_t pack4_e4m3(float x0, float x1, float x2, float x3) {
    uint16_t lo, hi;
    asm("cvt.rn.satfinite.e4m3x2.f32 %0, %1, %2;" : "=h"(lo) : "f"(x1), "f"(x0));
    asm("cvt.rn.satfinite.e4m3x2.f32 %0, %1, %2;" : "=h"(hi) : "f"(x3), "f"(x2));
    return (uint32_t)lo | ((uint32_t)hi << 16);
}

__device__ __forceinline__ void mma_16832_e4m3(float* c, const uint32_t* a, const uint32_t* b) {
    asm volatile(
        "mma.sync.aligned.m16n8k32.row.col.f32.e4m3.e4m3.f32 "
        "{%0,%1,%2,%3}, {%4,%5,%6,%7}, {%8,%9}, {%0,%1,%2,%3};"
        : "+f"(c[0]), "+f"(c[1]), "+f"(c[2]), "+f"(c[3])
        : "r"(a[0]), "r"(a[1]), "r"(a[2]), "r"(a[3]), "r"(b[0]), "r"(b[1]));
}

// ---------------------------------------------------------------------------
// Kernel 1: persistent, barrier-free warp pipelines; 4 warps x 32 m-rows.
// GEMM on fp8 e4m3 (m16n8k32), fp32 accumulate. W1 scaled x8 -> epilogue x0.125.
// Gather is explicitly batched (8 row-pairs per batch) to keep >=16 LDG.128
// in flight before the convert/store chain starts.
// ---------------------------------------------------------------------------
__global__ void __launch_bounds__(THREADS, 4)
score_kernel(const float* __restrict__ embeds,
             const int*   __restrict__ pos,
             const int*   __restrict__ neg,
             const float* __restrict__ W1,
             const float* __restrict__ b1,
             const float* __restrict__ W2,
             const float* __restrict__ b2)
{
    extern __shared__ char smem[];
    const int tid = threadIdx.x;
    const int wid = tid >> 5;
    const int lid = tid & 31;
    const int g   = lid >> 2;          // fragment row/col group
    const int tg  = lid & 3;           // thread-in-group

    // One-time staging: b1, W2, W1 (e4m3 x8, plain 208B-pitch rows).
    if (tid < 64) {
        ((float*)(smem + SMEM_B1))[tid] = b1[tid];
        ((float*)(smem + SMEM_W2))[tid] = W2[tid];
    }
    for (int c = tid; c < 64 * 12; c += THREADS) {
        int n  = c / 12;
        int gq = c - n * 12;                    // 16-k chunk within row
        const float4* wp = (const float4*)(W1 + n * KDIM + gq * 16);
        float4 w0 = wp[0], w1 = wp[1], w2c = wp[2], w3 = wp[3];
        uint4 v = make_uint4(
            pack4_e4m3(w0.x * 8.0f, w0.y * 8.0f, w0.z * 8.0f, w0.w * 8.0f),
            pack4_e4m3(w1.x * 8.0f, w1.y * 8.0f, w1.z * 8.0f, w1.w * 8.0f),
            pack4_e4m3(w2c.x * 8.0f, w2c.y * 8.0f, w2c.z * 8.0f, w2c.w * 8.0f),
            pack4_e4m3(w3.x * 8.0f, w3.y * 8.0f, w3.z * 8.0f, w3.w * 8.0f));
        *(uint4*)(smem + SMEM_B + n * BPITCH + gq * 16) = v;
    }
    __syncthreads();   // only barrier in the kernel

    const float b2v = b2[0];
    const int q   = lid & 15;          // float4 slot within a 64-float row
    const int grp = lid >> 4;          // which of two rows per gather iter

    for (int t = blockIdx.x; t < NTILE_TOT; t += GRID_SC) {
        const int p0 = t * M_TILE;

        // ---- gather + convert: warp owns rows [32*wid, 32*wid+32) ----
        int iu_r, iv_r;
        {
            int p = p0 + wid * 32 + lid;
            unsigned e = (unsigned)p / 17u;
            unsigned j = (unsigned)p - e * 17u;
            const int* pr = (j == 0) ? (pos + 2 * e)
                                     : (neg + 2 * (e * KNEG + (j - 1)));
            iu_r = pr[0];
            iv_r = pr[1];
        }
        // Two batches of 8 iterations; each batch: issue 16 LDG.128, then convert.
        #pragma unroll
        for (int bt = 0; bt < 2; bt++) {
            float4 ub[8], vb[8];
            #pragma unroll
            for (int i = 0; i < 8; i++) {
                int src = 2 * (bt * 8 + i) + grp;           // local row
                int iu = __shfl_sync(0xffffffffu, iu_r, src);
                int iv = __shfl_sync(0xffffffffu, iv_r, src);
                ub[i] = ((const float4*)(embeds + (size_t)iu * 64))[q];
                vb[i] = ((const float4*)(embeds + (size_t)iv * 64))[q];
            }
            #pragma unroll
            for (int i = 0; i < 8; i++) {
                int src = 2 * (bt * 8 + i) + grp;
                float4 u4 = ub[i], v4 = vb[i];
                char* xr = smem + SMEM_A + (wid * 32 + src) * APITCH;
                *(uint32_t*)(xr + q * 4) =
                    pack4_e4m3(u4.x, u4.y, u4.z, u4.w);
                *(uint32_t*)(xr + 64 + q * 4) =
                    pack4_e4m3(v4.x, v4.y, v4.z, v4.w);
                *(uint32_t*)(xr + 128 + q * 4) =
                    pack4_e4m3(u4.x * v4.x, u4.y * v4.y, u4.z * v4.z, u4.w * v4.w);
            }
        }

        // ---- GEMM: warp tile 32(m) x 64(n), K=192 (6 k32 steps) ----
        float c0[NTILES][4], c1[NTILES][4];
        #pragma unroll
        for (int nt = 0; nt < NTILES; nt++) {
            c0[nt][0] = c0[nt][1] = c0[nt][2] = c0[nt][3] = 0.0f;
            c1[nt][0] = c1[nt][1] = c1[nt][2] = c1[nt][3] = 0.0f;
        }
        #pragma unroll
        for (int ks = 0; ks < KSTEPS; ks++) {
            uint32_t a0[4], a1[4];
            {
                const char* ar = smem + SMEM_A + (wid * 32 + g) * APITCH + ks * 32 + tg * 4;
                a0[0] = *(const uint32_t*)(ar);
                a0[1] = *(const uint32_t*)(ar + 8 * APITCH);
                a0[2] = *(const uint32_t*)(ar + 16);
                a0[3] = *(const uint32_t*)(ar + 8 * APITCH + 16);
                const char* ar1 = ar + 16 * APITCH;
                a1[0] = *(const uint32_t*)(ar1);
                a1[1] = *(const uint32_t*)(ar1 + 8 * APITCH);
                a1[2] = *(const uint32_t*)(ar1 + 16);
                a1[3] = *(const uint32_t*)(ar1 + 8 * APITCH + 16);
            }
            #pragma unroll
            for (int nt = 0; nt < NTILES; nt++) {
                uint32_t b[2];
                const char* br = smem + SMEM_B + (nt * 8 + g) * BPITCH + ks * 32 + tg * 4;
                b[0] = *(const uint32_t*)(br);
                b[1] = *(const uint32_t*)(br + 16);
                mma_16832_e4m3(c0[nt], a0, b);
                mma_16832_e4m3(c1[nt], a1, b);
            }
        }

        // ---- epilogue in fragment layout (x0.125 undoes the W1 x8 scale) ----
        const float* b1s = (const float*)(smem + SMEM_B1);
        const float* w2s = (const float*)(smem + SMEM_W2);
        float z00 = 0.0f, z01 = 0.0f, z10 = 0.0f, z11 = 0.0f;
        #pragma unroll
        for (int nt = 0; nt < NTILES; nt++) {
            int n0 = nt * 8 + 2 * tg;
            float bb0 = b1s[n0], bb1 = b1s[n0 + 1];
            float ww0 = w2s[n0], ww1 = w2s[n0 + 1];
            float h;
            h = fmaf(c0[nt][0], 0.125f, bb0); h = h > 0.0f ? h : 0.0f; z00 += h * ww0;
            h = fmaf(c0[nt][1], 0.125f, bb1); h = h > 0.0f ? h : 0.0f; z00 += h * ww1;
            h = fmaf(c0[nt][2], 0.125f, bb0); h = h > 0.0f ? h : 0.0f; z01 += h * ww0;
            h = fmaf(c0[nt][3], 0.125f, bb1); h = h > 0.0f ? h : 0.0f; z01 += h * ww1;
            h = fmaf(c1[nt][0], 0.125f, bb0); h = h > 0.0f ? h : 0.0f; z10 += h * ww0;
            h = fmaf(c1[nt][1], 0.125f, bb1); h = h > 0.0f ? h : 0.0f; z10 += h * ww1;
            h = fmaf(c1[nt][2], 0.125f, bb0); h = h > 0.0f ? h : 0.0f; z11 += h * ww0;
            h = fmaf(c1[nt][3], 0.125f, bb1); h = h > 0.0f ? h : 0.0f; z11 += h * ww1;
        }
        z00 += __shfl_xor_sync(0xffffffffu, z00, 1);
        z00 += __shfl_xor_sync(0xffffffffu, z00, 2);
        z01 += __shfl_xor_sync(0xffffffffu, z01, 1);
        z01 += __shfl_xor_sync(0xffffffffu, z01, 2);
        z10 += __shfl_xor_sync(0xffffffffu, z10, 1);
        z10 += __shfl_xor_sync(0xffffffffu, z10, 2);
        z11 += __shfl_xor_sync(0xffffffffu, z11, 1);
        z11 += __shfl_xor_sync(0xffffffffu, z11, 2);

        if (tg == 0) {
            int r = p0 + wid * 32 + g;
            float s00 = 1.0f / (1.0f + expf(-(z00 + b2v)));
            float s01 = 1.0f / (1.0f + expf(-(z01 + b2v)));
            float s10 = 1.0f / (1.0f + expf(-(z10 + b2v)));
            float s11 = 1.0f / (1.0f + expf(-(z11 + b2v)));
            g_scores[r]      = expf(s00);
            g_scores[r + 8]  = expf(s01);
            g_scores[r + 16] = expf(s10);
            g_scores[r + 24] = expf(s11);
        }
    }
}

// ---------------------------------------------------------------------------
// Kernel 2: per-group ratio + global reduction.
// ---------------------------------------------------------------------------
__global__ void __launch_bounds__(256)
loss_kernel(float* __restrict__ out)
{
    int e = blockIdx.x * blockDim.x + threadIdx.x;
    float term = 0.0f;
    if (e < E_GROUPS) {
        const float* s = g_scores + (long long)e * GROUP;
        float ps = s[0];
        float denom = ps;
        #pragma unroll
        for (int j = 1; j < GROUP; j++) denom += s[j];
        term = ps / (denom + 1e-8f) + 1e-8f;
    }
    #pragma unroll
    for (int o = 16; o; o >>= 1) term += __shfl_xor_sync(0xffffffffu, term, o);

    __shared__ float wsum[8];
    int l = threadIdx.x & 31;
    int w = threadIdx.x >> 5;
    if (l == 0) wsum[w] = term;
    __syncthreads();
    if (threadIdx.x < 8) {
        float t = wsum[threadIdx.x];
        #pragma unroll
        for (int o = 4; o; o >>= 1) t += __shfl_xor_sync(0x000000ffu, t, o);
        if (threadIdx.x == 0) atomicAdd(out, -t);
    }
}

extern "C" void kernel_launch(void* const* d_in, const int* in_sizes, int n_in,
                              void* d_out, int out_size)
{
    const float* embeds = (const float*)d_in[0];
    const int*   pos    = (const int*)  d_in[1];
    const int*   neg    = (const int*)  d_in[2];
    const float* W1     = (const float*)d_in[3];
    const float* b1     = (const float*)d_in[4];
    const float* W2     = (const float*)d_in[5];
    const float* b2     = (const float*)d_in[6];
    float*       out    = (float*)d_out;

    cudaFuncSetAttribute(score_kernel, cudaFuncAttributeMaxDynamicSharedMemorySize,
                         SMEM_TOTAL);

    // score first (independent of zeroing) so ncu's fixed skip lands on the
    // hot kernel; zero must still precede loss.
    score_kernel<<<GRID_SC, THREADS, SMEM_TOTAL>>>(embeds, pos, neg, W1, b1, W2, b2);
    zero_out_kernel<<<1, 1>>>(out);
    loss_kernel<<<E_GROUPS / 256, 256>>>(out);
}

// round 11
// speedup vs baseline: 1.1584x; 1.0113x over previous
#include <cuda_runtime.h>
#include <cuda_bf16.h>
#include <cstdint>

// Problem constants (fixed shapes for TrivialDecoder_1236950581455)
#define E_GROUPS 65536
#define KNEG     16
#define GROUP    17
#define PAIRS    (E_GROUPS * GROUP)   // 1,114,112
#define D        64
#define KDIM     192
#define M_TILE   128
#define NTILE_TOT (PAIRS / M_TILE)    // 8704
#define THREADS  256                  // 8 warps, each owns 16 m-rows
#define KSTEPS   6                    // 192 / 32 (fp8 k32 mma)
#define NTILES   8                    // 64 / 8
#define GRID_SC  444                  // 148 SMs x 3 CTAs

#define APITCH   208                  // A: bytes per row (e4m3), conflict-free LDS
#define BPITCH   208                  // B: bytes per row (e4m3)

// SMEM byte layout: total 40960 B (40 KB) -> 3 CTAs/SM (reg-limited)
#define SMEM_B1    0                          // 64 floats
#define SMEM_W2    256                        // 64 floats
#define SMEM_A     1024                       // 128 x 208 = 26624 B
#define SMEM_B     (1024 + 128 * APITCH)      // 64 x 208 = 13312 B
#define SMEM_TOTAL (SMEM_B + 64 * BPITCH)     // 40960

__device__ float g_scores[PAIRS];

__global__ void zero_out_kernel(float* out) { out[0] = 0.0f; }

// ---------------- portable PTX helpers ----------------
// cvt.e4m3x2: a -> high byte, b -> low byte. We want k-ascending in ascending bytes.
__device__ __forceinline__ uint32_t pack4_e4m3(float x0, float x1, float x2, float x3) {
    uint16_t lo, hi;
    asm("cvt.rn.satfinite.e4m3x2.f32 %0, %1, %2;" : "=h"(lo) : "f"(x1), "f"(x0));
    asm("cvt.rn.satfinite.e4m3x2.f32 %0, %1, %2;" : "=h"(hi) : "f"(x3), "f"(x2));
    return (uint32_t)lo | ((uint32_t)hi << 16);
}

__device__ __forceinline__ void mma_16832_e4m3(float* c, const uint32_t* a, const uint32_t* b) {
    asm volatile(
        "mma.sync.aligned.m16n8k32.row.col.f32.e4m3.e4m3.f32 "
        "{%0,%1,%2,%3}, {%4,%5,%6,%7}, {%8,%9}, {%0,%1,%2,%3};"
        : "+f"(c[0]), "+f"(c[1]), "+f"(c[2]), "+f"(c[3])
        : "r"(a[0]), "r"(a[1]), "r"(a[2]), "r"(a[3]), "r"(b[0]), "r"(b[1]));
}

// ---------------------------------------------------------------------------
// Kernel 1: persistent, barrier-free warp pipelines; 8 warps x 16 m-rows.
// GEMM on fp8 e4m3 (m16n8k32), fp32 accumulate. W1 scaled x8 -> epilogue x0.125.
// Smaller per-warp state (32-reg accumulators, 32-reg gather buffer) so
// 3 CTAs x 256 threads fit the register file -> 24 warps/SM.
// ---------------------------------------------------------------------------
__global__ void __launch_bounds__(THREADS, 3)
score_kernel(const float* __restrict__ embeds,
             const int*   __restrict__ pos,
             const int*   __restrict__ neg,
             const float* __restrict__ W1,
             const float* __restrict__ b1,
             const float* __restrict__ W2,
             const float* __restrict__ b2)
{
    extern __shared__ char smem[];
    const int tid = threadIdx.x;
    const int wid = tid >> 5;
    const int lid = tid & 31;
    const int g   = lid >> 2;          // fragment row/col group
    const int tg  = lid & 3;           // thread-in-group

    // One-time staging: b1, W2, W1 (e4m3 x8, plain 208B-pitch rows).
    if (tid < 64) {
        ((float*)(smem + SMEM_B1))[tid] = b1[tid];
        ((float*)(smem + SMEM_W2))[tid] = W2[tid];
    }
    for (int c = tid; c < 64 * 12; c += THREADS) {
        int n  = c / 12;
        int gq = c - n * 12;                    // 16-k chunk within row
        const float4* wp = (const float4*)(W1 + n * KDIM + gq * 16);
        float4 w0 = wp[0], w1 = wp[1], w2c = wp[2], w3 = wp[3];
        uint4 v = make_uint4(
            pack4_e4m3(w0.x * 8.0f, w0.y * 8.0f, w0.z * 8.0f, w0.w * 8.0f),
            pack4_e4m3(w1.x * 8.0f, w1.y * 8.0f, w1.z * 8.0f, w1.w * 8.0f),
            pack4_e4m3(w2c.x * 8.0f, w2c.y * 8.0f, w2c.z * 8.0f, w2c.w * 8.0f),
            pack4_e4m3(w3.x * 8.0f, w3.y * 8.0f, w3.z * 8.0f, w3.w * 8.0f));
        *(uint4*)(smem + SMEM_B + n * BPITCH + gq * 16) = v;
    }
    __syncthreads();   // only barrier in the kernel

    const float b2v = b2[0];
    const int q   = lid & 15;          // float4 slot within a 64-float row
    const int grp = lid >> 4;          // which of two rows per gather iter

    for (int t = blockIdx.x; t < NTILE_TOT; t += GRID_SC) {
        const int p0 = t * M_TILE;

        // ---- gather + convert: warp owns rows [16*wid, 16*wid+16) ----
        int iu_r = 0, iv_r = 0;
        if (lid < 16) {
            int p = p0 + wid * 16 + lid;
            unsigned e = (unsigned)p / 17u;
            unsigned j = (unsigned)p - e * 17u;
            const int* pr = (j == 0) ? (pos + 2 * e)
                                     : (neg + 2 * (e * KNEG + (j - 1)));
            iu_r = pr[0];
            iv_r = pr[1];
        }
        // Two batches of 4 iterations; each batch: issue 8 LDG.128, then convert.
        #pragma unroll
        for (int bt = 0; bt < 2; bt++) {
            float4 ub[4], vb[4];
            #pragma unroll
            for (int i = 0; i < 4; i++) {
                int src = 2 * (bt * 4 + i) + grp;           // local row 0..15
                int iu = __shfl_sync(0xffffffffu, iu_r, src);
                int iv = __shfl_sync(0xffffffffu, iv_r, src);
                ub[i] = ((const float4*)(embeds + (size_t)iu * 64))[q];
                vb[i] = ((const float4*)(embeds + (size_t)iv * 64))[q];
            }
            #pragma unroll
            for (int i = 0; i < 4; i++) {
                int src = 2 * (bt * 4 + i) + grp;
                float4 u4 = ub[i], v4 = vb[i];
                char* xr = smem + SMEM_A + (wid * 16 + src) * APITCH;
                *(uint32_t*)(xr + q * 4) =
                    pack4_e4m3(u4.x, u4.y, u4.z, u4.w);
                *(uint32_t*)(xr + 64 + q * 4) =
                    pack4_e4m3(v4.x, v4.y, v4.z, v4.w);
                *(uint32_t*)(xr + 128 + q * 4) =
                    pack4_e4m3(u4.x * v4.x, u4.y * v4.y, u4.z * v4.z, u4.w * v4.w);
            }
        }

        // ---- GEMM: warp tile 16(m) x 64(n), K=192 (6 k32 steps) ----
        float c0[NTILES][4];
        #pragma unroll
        for (int nt = 0; nt < NTILES; nt++) {
            c0[nt][0] = c0[nt][1] = c0[nt][2] = c0[nt][3] = 0.0f;
        }
        #pragma unroll
        for (int ks = 0; ks < KSTEPS; ks++) {
            uint32_t a0[4];
            {
                const char* ar = smem + SMEM_A + (wid * 16 + g) * APITCH + ks * 32 + tg * 4;
                a0[0] = *(const uint32_t*)(ar);
                a0[1] = *(const uint32_t*)(ar + 8 * APITCH);
                a0[2] = *(const uint32_t*)(ar + 16);
                a0[3] = *(const uint32_t*)(ar + 8 * APITCH + 16);
            }
            #pragma unroll
            for (int nt = 0; nt < NTILES; nt++) {
                uint32_t b[2];
                const char* br = smem + SMEM_B + (nt * 8 + g) * BPITCH + ks * 32 + tg * 4;
                b[0] = *(const uint32_t*)(br);
                b[1] = *(const uint32_t*)(br + 16);
                mma_16832_e4m3(c0[nt], a0, b);
            }
        }

        // ---- epilogue in fragment layout (x0.125 undoes the W1 x8 scale) ----
        const float* b1s = (const float*)(smem + SMEM_B1);
        const float* w2s = (const float*)(smem + SMEM_W2);
        float z0 = 0.0f, z1 = 0.0f;
        #pragma unroll
        for (int nt = 0; nt < NTILES; nt++) {
            int n0 = nt * 8 + 2 * tg;
            float bb0 = b1s[n0], bb1 = b1s[n0 + 1];
            float ww0 = w2s[n0], ww1 = w2s[n0 + 1];
            float h;
            h = fmaf(c0[nt][0], 0.125f, bb0); h = h > 0.0f ? h : 0.0f; z0 += h * ww0;
            h = fmaf(c0[nt][1], 0.125f, bb1); h = h > 0.0f ? h : 0.0f; z0 += h * ww1;
            h = fmaf(c0[nt][2], 0.125f, bb0); h = h > 0.0f ? h : 0.0f; z1 += h * ww0;
            h = fmaf(c0[nt][3], 0.125f, bb1); h = h > 0.0f ? h : 0.0f; z1 += h * ww1;
        }
        z0 += __shfl_xor_sync(0xffffffffu, z0, 1);
        z0 += __shfl_xor_sync(0xffffffffu, z0, 2);
        z1 += __shfl_xor_sync(0xffffffffu, z1, 1);
        z1 += __shfl_xor_sync(0xffffffffu, z1, 2);

        if (tg == 0) {
            int r = p0 + wid * 16 + g;
            float s0 = 1.0f / (1.0f + expf(-(z0 + b2v)));
            float s1 = 1.0f / (1.0f + expf(-(z1 + b2v)));
            g_scores[r]     = expf(s0);
            g_scores[r + 8] = expf(s1);
        }
    }
}

// ---------------------------------------------------------------------------
// Kernel 2: per-group ratio + global reduction.
// ---------------------------------------------------------------------------
__global__ void __launch_bounds__(256)
loss_kernel(float* __restrict__ out)
{
    int e = blockIdx.x * blockDim.x + threadIdx.x;
    float term = 0.0f;
    if (e < E_GROUPS) {
        const float* s = g_scores + (long long)e * GROUP;
        float ps = s[0];
        float denom = ps;
        #pragma unroll
        for (int j = 1; j < GROUP; j++) denom += s[j];
        term = ps / (denom + 1e-8f) + 1e-8f;
    }
    #pragma unroll
    for (int o = 16; o; o >>= 1) term += __shfl_xor_sync(0xffffffffu, term, o);

    __shared__ float wsum[8];
    int l = threadIdx.x & 31;
    int w = threadIdx.x >> 5;
    if (l == 0) wsum[w] = term;
    __syncthreads();
    if (threadIdx.x < 8) {
        float t = wsum[threadIdx.x];
        #pragma unroll
        for (int o = 4; o; o >>= 1) t += __shfl_xor_sync(0x000000ffu, t, o);
        if (threadIdx.x == 0) atomicAdd(out, -t);
    }
}

extern "C" void kernel_launch(void* const* d_in, const int* in_sizes, int n_in,
                              void* d_out, int out_size)
{
    const float* embeds = (const float*)d_in[0];
    const int*   pos    = (const int*)  d_in[1];
    const int*   neg    = (const int*)  d_in[2];
    const float* W1     = (const float*)d_in[3];
    const float* b1     = (const float*)d_in[4];
    const float* W2     = (const float*)d_in[5];
    const float* b2     = (const float*)d_in[6];
    float*       out    = (float*)d_out;

    cudaFuncSetAttribute(score_kernel, cudaFuncAttributeMaxDynamicSharedMemorySize,
                         SMEM_TOTAL);

    // score first (independent of zeroing) so ncu's fixed skip lands on the
    // hot kernel; zero must still precede loss.
    score_kernel<<<GRID_SC, THREADS, SMEM_TOTAL>>>(embeds, pos, neg, W1, b1, W2, b2);
    zero_out_kernel<<<1, 1>>>(out);
    loss_kernel<<<E_GROUPS / 256, 256>>>(out);
}